// round 16
// baseline (speedup 1.0000x reference)
#include <cuda_runtime.h>
#include <cstdint>

typedef unsigned long long u64;
typedef unsigned long long ull;
typedef unsigned int u32;

// ============================ problem constants ============================
#define N_   32
#define C_   256
#define H_   56
#define W_   56
#define PH_  58
#define PW_  58
#define PIX_ (H_*W_)                 // 3136
#define M_CNT_ (N_*PIX_)             // 100352
#define NW_  4                       // u64 words per pixel (256 ch)
#define HALFW_ 28                    // half-row width
#define SLAB_ 30                     // halo-extended half-row cols

// ============================ device scratch ============================
__device__ __align__(16) u64 g_Xp1[(size_t)N_*PH_*PW_*NW_];
__device__ __align__(16) u64 g_Xp2[(size_t)N_*PH_*PW_*NW_];
__device__ __align__(16) u64 g_Wp1[9*C_*NW_];
__device__ __align__(16) u64 g_Wp2[9*C_*NW_];
__device__ int  g_c1[9*C_];
__device__ int  g_c2[9*C_];
__device__ __align__(16) short g_S1[(size_t)M_CNT_*C_];
__device__ __align__(16) short g_S2[(size_t)M_CNT_*C_];
__device__ ull g_sum1[C_], g_sq1[C_], g_sum2[C_], g_sq2[C_];
__device__ float g_a1[C_], g_b1[C_], g_a2[C_], g_b2[C_];

// ============================ setup kernels ============================
__global__ void pack_w_k(const float* __restrict__ w1, const float* __restrict__ w2,
                         u64* __restrict__ Wp1, u64* __restrict__ Wp2) {
    int blk = blockIdx.x, c = threadIdx.x;
    if (blk == 0) {
        g_sum1[c] = 0ull; g_sq1[c] = 0ull; g_sum2[c] = 0ull; g_sq2[c] = 0ull;
    }
    const float* w = (blk < 9) ? w1 : w2;
    u64* Wp = (blk < 9) ? Wp1 : Wp2;
    int t = (blk < 9) ? blk : blk - 9;
    int ky = t / 3, kx = t % 3;
    #pragma unroll
    for (int j = 0; j < NW_; ++j) {
        u64 bits = 0ull;
        #pragma unroll 4
        for (int cl = 0; cl < 64; ++cl) {
            float v = w[(((size_t)c * C_ + (j * 64 + cl)) * 3 + ky) * 3 + kx];
            bits |= (u64)(v > 0.0f) << cl;
        }
        Wp[((size_t)t * C_ + c) * NW_ + j] = bits;
    }
}

__global__ void corr_w_k() {
    const u64* Wp = blockIdx.x ? g_Wp2 : g_Wp1;
    int* corr     = blockIdx.x ? g_c2  : g_c1;
    int c = threadIdx.x;
    int pc[9];
    #pragma unroll
    for (int t = 0; t < 9; ++t) {
        int s = 0;
        #pragma unroll
        for (int j = 0; j < NW_; ++j) s += __popcll(Wp[((size_t)t * C_ + c) * NW_ + j]);
        pc[t] = s;
    }
    for (int type = 0; type < 9; ++type) {
        int rt = type / 3, ct = type % 3;
        int s = 0;
        #pragma unroll
        for (int ky = 0; ky < 3; ++ky)
            #pragma unroll
            for (int kx = 0; kx < 3; ++kx) {
                bool rinv = (rt == 0 && ky == 0) || (rt == 2 && ky == 2);
                bool cinv = (ct == 0 && kx == 0) || (ct == 2 && kx == 2);
                if (rinv || cinv) s += 256 - 2 * pc[ky * 3 + kx];
            }
        corr[type * C_ + c] = s;
    }
}

__global__ void pack_x_k(const float* __restrict__ x, u64* __restrict__ Xp) {
    int px = threadIdx.x, j = threadIdx.y;
    int py = blockIdx.x, n = blockIdx.y;
    size_t oidx = (((size_t)n * PH_ + py) * PW_ + px) * NW_ + j;
    if (px == 0 || px == PW_ - 1 || py == 0 || py == PH_ - 1) { Xp[oidx] = 0ull; return; }
    const float* xp = x + (((size_t)n * C_ + j * 64) * H_ + (py - 1)) * W_ + (px - 1);
    u64 bits = 0ull;
    #pragma unroll 8
    for (int cl = 0; cl < 64; ++cl)
        bits |= (u64)(xp[(size_t)cl * PIX_] > 0.0f) << cl;
    Xp[oidx] = bits;
}

__global__ void bnparams_k(const ull* __restrict__ sum, const ull* __restrict__ sq,
                           const float* __restrict__ gamma, const float* __restrict__ beta,
                           float* __restrict__ a, float* __restrict__ b) {
    int c = threadIdx.x;
    const double M = (double)M_CNT_;
    double mS = (double)(long long)sum[c] / M;
    double vS = (double)(long long)sq[c] / M - mS * mS;
    double m = 0.5 * mS;
    double v = 0.25 * vS;
    double r = 1.0 / sqrt(v + 1e-5);
    double g = (double)gamma[c];
    a[c] = (float)(0.5 * r * g);
    b[c] = (float)((double)beta[c] - m * r * g);
}

// ============================ CSA primitives ============================
__device__ __forceinline__ u32 xor3(u32 a, u32 b, u32 c) {
    u32 d; asm("lop3.b32 %0,%1,%2,%3,0x96;" : "=r"(d) : "r"(a), "r"(b), "r"(c)); return d;
}
__device__ __forceinline__ u32 maj3(u32 a, u32 b, u32 c) {
    u32 d; asm("lop3.b32 %0,%1,%2,%3,0xE8;" : "=r"(d) : "r"(a), "r"(b), "r"(c)); return d;
}
__device__ __forceinline__ u32 fa_c(u32& on, u32 a, u32 b) {
    u32 c1 = maj3(on, a, b);
    on = xor3(on, a, b);
    return c1;
}
#define IMAD_ACC(ACC, PC) \
    asm("mad.lo.s32 %0, %1, %2, %0;" : "+r"(ACC) : "r"(PC), "r"(one))

// one tap for a uint2 quarter: 2 XOR + 1 fa (2 LOP3) + popc + imad
#define TAPQ(ACC, ON, XV, WT) { \
    u32 ca = fa_c(ON, (XV).x ^ (WT).x, (XV).y ^ (WT).y); \
    int pa = __popc(ca); \
    IMAD_ACC(ACC, pa); \
}

// ============================ hot kernel: quarter-split XNOR conv ============================
// thread = (channel, quarter-of-256-cin); 4 pixels/iter; butterfly merge.
__global__ __launch_bounds__(256, 4)
void conv_pop_k(const u64* __restrict__ Xp,
                const u64* __restrict__ Wp,
                const int* __restrict__ corr,
                short* __restrict__ S,
                ull* __restrict__ sum, ull* __restrict__ sq)
{
    __shared__ u64 sx[3 * SLAB_ * NW_];   // 2880 B
    const int t     = threadIdx.x;
    const int q     = t & 3;              // quarter (u64 word index)
    const int q2    = q * 2;              // u32 word offset
    const int c     = blockIdx.z * 64 + (t >> 2);
    const int oy    = blockIdx.x >> 1;
    const int xh    = blockIdx.x & 1;
    const int n     = blockIdx.y;
    const int cbase = xh * HALFW_;

    // opaque 1 (grid.x = 112 < 2^20): keeps IMADs genuine
    const int one = (int)(blockIdx.x >> 20) + 1;
    const int two = one + one;

    uint2 w[9];
    #pragma unroll
    for (int tp = 0; tp < 9; ++tp)
        w[tp] = *(const uint2*)((const u32*)&Wp[((size_t)tp * C_ + c) * NW_] + q2);

    const int rt = (oy == 0) ? 0 : ((oy == H_ - 1) ? 2 : 1);
    const int cL = corr[(rt * 3 + 0) * C_ + c];
    const int cM = corr[(rt * 3 + 1) * C_ + c];
    const int cR = corr[(rt * 3 + 2) * C_ + c];

    {
        ulonglong2* dst = (ulonglong2*)sx;
        for (int i = t; i < 3 * SLAB_ * 2; i += 256) {
            int r = i / (SLAB_ * 2), rem = i - r * (SLAB_ * 2);
            const ulonglong2* src = (const ulonglong2*)
                (Xp + (((size_t)n * PH_ + oy + r) * PW_ + cbase) * NW_);
            dst[r * SLAB_ * 2 + rem] = src[rem];
        }
    }
    __syncthreads();

    int ss = 0, qq = 0;
    const u32* sxw = (const u32*)sx;
    const size_t rowbase = (((size_t)n * H_ + oy) * W_) * C_ + c;

    #pragma unroll 1
    for (int ox = 0; ox < HALFW_; ox += 4) {
        u32 on0 = 0, on1 = 0, on2 = 0, on3 = 0;
        int a0 = 0, a1 = 0, a2 = 0, a3 = 0;
        #pragma unroll
        for (int ky = 0; ky < 3; ++ky) {
            const u32* base = sxw + (ky * SLAB_ + ox) * 8 + q2;
            const uint2 c0 = *(const uint2*)(base);
            const uint2 c1 = *(const uint2*)(base + 8);
            const uint2 c2 = *(const uint2*)(base + 16);
            const uint2 c3 = *(const uint2*)(base + 24);
            const uint2 c4 = *(const uint2*)(base + 32);
            const uint2 c5 = *(const uint2*)(base + 40);
            const int k3 = ky * 3;
            TAPQ(a0, on0, c0, w[k3 + 0])
            TAPQ(a0, on0, c1, w[k3 + 1])
            TAPQ(a0, on0, c2, w[k3 + 2])
            TAPQ(a1, on1, c1, w[k3 + 0])
            TAPQ(a1, on1, c2, w[k3 + 1])
            TAPQ(a1, on1, c3, w[k3 + 2])
            TAPQ(a2, on2, c2, w[k3 + 0])
            TAPQ(a2, on2, c3, w[k3 + 1])
            TAPQ(a2, on2, c4, w[k3 + 2])
            TAPQ(a3, on3, c3, w[k3 + 0])
            TAPQ(a3, on3, c4, w[k3 + 1])
            TAPQ(a3, on3, c5, w[k3 + 2])
        }
        // quarter ones counts (<=576 each)
        int f0 = __popc(on0), f1 = __popc(on1), f2 = __popc(on2), f3 = __popc(on3);
        asm("mad.lo.s32 %0, %1, %2, %0;" : "+r"(f0) : "r"(a0), "r"(two));
        asm("mad.lo.s32 %0, %1, %2, %0;" : "+r"(f1) : "r"(a1), "r"(two));
        asm("mad.lo.s32 %0, %1, %2, %0;" : "+r"(f2) : "r"(a2), "r"(two));
        asm("mad.lo.s32 %0, %1, %2, %0;" : "+r"(f3) : "r"(a3), "r"(two));
        // butterfly merge across the 4 quarters (lanes 4k..4k+3)
        u32 v01 = (u32)f0 | ((u32)f1 << 16);
        u32 v23 = (u32)f2 | ((u32)f3 << 16);
        v01 += __shfl_xor_sync(0xffffffffu, v01, 1);
        v01 += __shfl_xor_sync(0xffffffffu, v01, 2);
        v23 += __shfl_xor_sync(0xffffffffu, v23, 1);
        v23 += __shfl_xor_sync(0xffffffffu, v23, 2);
        // thread q stores pixel ox+q
        const u32 vv = (q & 2) ? v23 : v01;
        const int f = (q & 1) ? (int)(vv >> 16) : (int)(vv & 0xffffu);
        const int gx = cbase + ox + q;
        const int cc = (gx == 0) ? cL : ((gx == W_ - 1) ? cR : cM);
        const int sv = 2304 - 2 * f - cc;
        S[rowbase + (size_t)gx * C_] = (short)sv;
        ss += sv;
        asm("mad.lo.s32 %0, %1, %2, %0;" : "+r"(qq) : "r"(sv), "r"(sv));
    }
    // reduce stats across the 4 quarter-threads, one atomic per channel per CTA
    ss += __shfl_xor_sync(0xffffffffu, ss, 1);
    ss += __shfl_xor_sync(0xffffffffu, ss, 2);
    qq += __shfl_xor_sync(0xffffffffu, qq, 1);
    qq += __shfl_xor_sync(0xffffffffu, qq, 2);
    if (q == 0) {
        atomicAdd(&sum[c], (ull)(long long)ss);
        atomicAdd(&sq[c],  (ull)(long long)qq);
    }
}

// ============================ thresh (fp32 params) ============================
__global__ void thresh_ballot_k(const short* __restrict__ S,
                                const float* __restrict__ a, const float* __restrict__ b,
                                u64* __restrict__ Xp2) {
    int c = threadIdx.x;
    int py = blockIdx.x, n = blockIdx.y;
    int warp = c >> 5, lane = c & 31;
    float av = a[c], bv = b[c];
    bool rowv = (py >= 1 && py <= H_);
    #pragma unroll 4
    for (int px = 0; px < PW_; ++px) {
        unsigned bit = 0u;
        if (rowv && px >= 1 && px <= W_) {
            int v = S[(((size_t)n * H_ + (py - 1)) * W_ + (px - 1)) * C_ + c];
            bit = (av * (float)v + bv > 0.0f) ? 1u : 0u;
        }
        unsigned m = __ballot_sync(0xffffffffu, bit);
        if (lane == 0)
            ((unsigned*)(Xp2 + (((size_t)n * PH_ + py) * PW_ + px) * NW_))[warp] = m;
    }
}

// ============================ final (fp32 params, float4 I/O) ============================
__global__ __launch_bounds__(256)
void final_k(const short* __restrict__ S2,
             const float* __restrict__ a, const float* __restrict__ b,
             const float* __restrict__ x, float* __restrict__ out) {
    __shared__ short s[32][258];
    __shared__ float sa[C_], sb[C_];
    const int n = blockIdx.y, pt = blockIdx.x;
    const int tid = threadIdx.x;

    sa[tid] = a[tid];
    sb[tid] = b[tid];
    const short2* src = (const short2*)(S2 + ((size_t)n * PIX_ + pt * 32) * C_);
    #pragma unroll
    for (int i = tid; i < 32 * 128; i += 256) {
        int r = i >> 7, c2 = i & 127;
        short2 v = src[(size_t)r * 128 + c2];
        s[r][c2 * 2]     = v.x;
        s[r][c2 * 2 + 1] = v.y;
    }
    __syncthreads();

    const int pg = tid & 7;
    const int c0 = tid >> 3;
    const int p0 = pt * 32 + pg * 4;
    #pragma unroll
    for (int cc = c0; cc < C_; cc += 32) {
        const float av = sa[cc], bv = sb[cc];
        const size_t oi = ((size_t)n * C_ + cc) * PIX_ + p0;
        const float4 xv = *(const float4*)(x + oi);
        float4 o;
        o.x = fminf(1.f, fmaxf(-1.f, av * (float)s[pg * 4 + 0][cc] + bv + xv.x));
        o.y = fminf(1.f, fmaxf(-1.f, av * (float)s[pg * 4 + 1][cc] + bv + xv.y));
        o.z = fminf(1.f, fmaxf(-1.f, av * (float)s[pg * 4 + 2][cc] + bv + xv.z));
        o.w = fminf(1.f, fmaxf(-1.f, av * (float)s[pg * 4 + 3][cc] + bv + xv.w));
        *(float4*)(out + oi) = o;
    }
}

// ============================ launch ============================
extern "C" void kernel_launch(void* const* d_in, const int* in_sizes, int n_in,
                              void* d_out, int out_size) {
    const float* x  = (const float*)d_in[0];
    const float* w1 = (const float*)d_in[1];
    const float* g1 = (const float*)d_in[2];
    const float* b1 = (const float*)d_in[3];
    const float* w2 = (const float*)d_in[4];
    const float* g2 = (const float*)d_in[5];
    const float* b2 = (const float*)d_in[6];
    float* out = (float*)d_out;

    void *pX1, *pX2, *pW1, *pW2, *pc1, *pc2, *pS1, *pS2;
    void *psum1, *psq1, *psum2, *psq2, *pa1, *pb1, *pa2, *pb2;
    cudaGetSymbolAddress(&pX1, g_Xp1);  cudaGetSymbolAddress(&pX2, g_Xp2);
    cudaGetSymbolAddress(&pW1, g_Wp1);  cudaGetSymbolAddress(&pW2, g_Wp2);
    cudaGetSymbolAddress(&pc1, g_c1);   cudaGetSymbolAddress(&pc2, g_c2);
    cudaGetSymbolAddress(&pS1, g_S1);   cudaGetSymbolAddress(&pS2, g_S2);
    cudaGetSymbolAddress(&psum1, g_sum1); cudaGetSymbolAddress(&psq1, g_sq1);
    cudaGetSymbolAddress(&psum2, g_sum2); cudaGetSymbolAddress(&psq2, g_sq2);
    cudaGetSymbolAddress(&pa1, g_a1);   cudaGetSymbolAddress(&pb1, g_b1);
    cudaGetSymbolAddress(&pa2, g_a2);   cudaGetSymbolAddress(&pb2, g_b2);

    // conv1 stays launch #3 (the one ncu profiles)
    pack_w_k<<<18, 256>>>(w1, w2, (u64*)pW1, (u64*)pW2);             // #0 (zeros stats)
    corr_w_k<<<2, 256>>>();                                          // #1
    pack_x_k<<<dim3(PH_, N_), dim3(PW_, NW_)>>>(x, (u64*)pX1);       // #2
    conv_pop_k<<<dim3(H_ * 2, N_, 4), 256>>>((const u64*)pX1, (const u64*)pW1,   // #3
                                             (const int*)pc1, (short*)pS1,
                                             (ull*)psum1, (ull*)psq1);
    bnparams_k<<<1, 256>>>((const ull*)psum1, (const ull*)psq1, g1, b1,
                           (float*)pa1, (float*)pb1);                // #4
    thresh_ballot_k<<<dim3(PH_, N_), 256>>>((const short*)pS1,
        (const float*)pa1, (const float*)pb1, (u64*)pX2);            // #5
    conv_pop_k<<<dim3(H_ * 2, N_, 4), 256>>>((const u64*)pX2, (const u64*)pW2,   // #6
                                             (const int*)pc2, (short*)pS2,
                                             (ull*)psum2, (ull*)psq2);
    bnparams_k<<<1, 256>>>((const ull*)psum2, (const ull*)psq2, g2, b2,
                           (float*)pa2, (float*)pb2);                // #7
    final_k<<<dim3(PIX_ / 32, N_), 256>>>((const short*)pS2,
        (const float*)pa2, (const float*)pb2, x, out);               // #8
}

// round 17
// speedup vs baseline: 1.0413x; 1.0413x over previous
#include <cuda_runtime.h>
#include <cstdint>

typedef unsigned long long u64;
typedef unsigned long long ull;
typedef unsigned int u32;

// ============================ problem constants ============================
#define N_   32
#define C_   256
#define H_   56
#define W_   56
#define PH_  58
#define PW_  58
#define PIX_ (H_*W_)                 // 3136
#define M_CNT_ (N_*PIX_)             // 100352
#define NW_  4                       // u64 words per pixel (256 ch)
#define HALFW_ 28                    // half-row width
#define SLAB_ 30                     // halo-extended half-row cols

// ============================ device scratch ============================
__device__ __align__(16) u64 g_Xp1[(size_t)N_*PH_*PW_*NW_];
__device__ __align__(16) u64 g_Xp2[(size_t)N_*PH_*PW_*NW_];
__device__ __align__(16) u64 g_Wp1[9*C_*NW_];
__device__ __align__(16) u64 g_Wp2[9*C_*NW_];
__device__ int  g_c1[9*C_];
__device__ int  g_c2[9*C_];
__device__ __align__(16) short g_S1[(size_t)M_CNT_*C_];
__device__ __align__(16) short g_S2[(size_t)M_CNT_*C_];
__device__ ull g_sum1[C_], g_sq1[C_], g_sum2[C_], g_sq2[C_];
__device__ float g_a1[C_], g_b1[C_], g_a2[C_], g_b2[C_];

// ============================ setup kernels ============================
__global__ void pack_w_k(const float* __restrict__ w1, const float* __restrict__ w2,
                         u64* __restrict__ Wp1, u64* __restrict__ Wp2) {
    int blk = blockIdx.x, c = threadIdx.x;
    if (blk == 0) {
        g_sum1[c] = 0ull; g_sq1[c] = 0ull; g_sum2[c] = 0ull; g_sq2[c] = 0ull;
    }
    const float* w = (blk < 9) ? w1 : w2;
    u64* Wp = (blk < 9) ? Wp1 : Wp2;
    int t = (blk < 9) ? blk : blk - 9;
    int ky = t / 3, kx = t % 3;
    #pragma unroll
    for (int j = 0; j < NW_; ++j) {
        u64 bits = 0ull;
        #pragma unroll 4
        for (int cl = 0; cl < 64; ++cl) {
            float v = w[(((size_t)c * C_ + (j * 64 + cl)) * 3 + ky) * 3 + kx];
            bits |= (u64)(v > 0.0f) << cl;
        }
        Wp[((size_t)t * C_ + c) * NW_ + j] = bits;
    }
}

__global__ void corr_w_k() {
    const u64* Wp = blockIdx.x ? g_Wp2 : g_Wp1;
    int* corr     = blockIdx.x ? g_c2  : g_c1;
    int c = threadIdx.x;
    int pc[9];
    #pragma unroll
    for (int t = 0; t < 9; ++t) {
        int s = 0;
        #pragma unroll
        for (int j = 0; j < NW_; ++j) s += __popcll(Wp[((size_t)t * C_ + c) * NW_ + j]);
        pc[t] = s;
    }
    for (int type = 0; type < 9; ++type) {
        int rt = type / 3, ct = type % 3;
        int s = 0;
        #pragma unroll
        for (int ky = 0; ky < 3; ++ky)
            #pragma unroll
            for (int kx = 0; kx < 3; ++kx) {
                bool rinv = (rt == 0 && ky == 0) || (rt == 2 && ky == 2);
                bool cinv = (ct == 0 && kx == 0) || (ct == 2 && kx == 2);
                if (rinv || cinv) s += 256 - 2 * pc[ky * 3 + kx];
            }
        corr[type * C_ + c] = s;
    }
}

__global__ void pack_x_k(const float* __restrict__ x, u64* __restrict__ Xp) {
    int px = threadIdx.x, j = threadIdx.y;
    int py = blockIdx.x, n = blockIdx.y;
    size_t oidx = (((size_t)n * PH_ + py) * PW_ + px) * NW_ + j;
    if (px == 0 || px == PW_ - 1 || py == 0 || py == PH_ - 1) { Xp[oidx] = 0ull; return; }
    const float* xp = x + (((size_t)n * C_ + j * 64) * H_ + (py - 1)) * W_ + (px - 1);
    u64 bits = 0ull;
    #pragma unroll 8
    for (int cl = 0; cl < 64; ++cl)
        bits |= (u64)(xp[(size_t)cl * PIX_] > 0.0f) << cl;
    Xp[oidx] = bits;
}

__global__ void bnparams_k(const ull* __restrict__ sum, const ull* __restrict__ sq,
                           const float* __restrict__ gamma, const float* __restrict__ beta,
                           float* __restrict__ a, float* __restrict__ b) {
    int c = threadIdx.x;
    const double M = (double)M_CNT_;
    double mS = (double)(long long)sum[c] / M;
    double vS = (double)(long long)sq[c] / M - mS * mS;
    double m = 0.5 * mS;
    double v = 0.25 * vS;
    double r = 1.0 / sqrt(v + 1e-5);
    double g = (double)gamma[c];
    a[c] = (float)(0.5 * r * g);
    b[c] = (float)((double)beta[c] - m * r * g);
}

// ============================ shallow CSA primitives ============================
__device__ __forceinline__ u32 xor3(u32 a, u32 b, u32 c) {
    u32 d; asm("lop3.b32 %0,%1,%2,%3,0x96;" : "=r"(d) : "r"(a), "r"(b), "r"(c)); return d;
}
__device__ __forceinline__ u32 maj3(u32 a, u32 b, u32 c) {
    u32 d; asm("lop3.b32 %0,%1,%2,%3,0xE8;" : "=r"(d) : "r"(a), "r"(b), "r"(c)); return d;
}
__device__ __forceinline__ u32 fa_c(u32& on, u32 a, u32 b) {
    u32 c1 = maj3(on, a, b);
    on = xor3(on, a, b);
    return c1;
}
// one tap (uint4 = 128 cin): 4 XOR + 2 fa (4 LOP3) + 2 POPC + fused adds
#define TAP(ACC, ON, XV, WT) { \
    u32 ca = fa_c(ON, (XV).x ^ (WT).x, (XV).y ^ (WT).y); \
    u32 cb = fa_c(ON, (XV).z ^ (WT).z, (XV).w ^ (WT).w); \
    ACC += __popc(ca) + __popc(cb); \
}

// ============================ hot kernel: 4-px window XNOR conv ============================
// thread = (cout, half-of-256-cin); 4 output pixels per iteration (6-column reuse).
__global__ __launch_bounds__(256, 3)
void conv_pop_k(const u64* __restrict__ Xp,
                const u64* __restrict__ Wp,
                const int* __restrict__ corr,
                short* __restrict__ S,
                ull* __restrict__ sum, ull* __restrict__ sq)
{
    __shared__ u64 sx[3 * SLAB_ * NW_];   // 2880 B
    const int t     = threadIdx.x;
    const int half  = t & 1;
    const int half2 = half * 2;
    const int c     = blockIdx.z * 128 + (t >> 1);
    const int oy    = blockIdx.x >> 1;
    const int xh    = blockIdx.x & 1;
    const int n     = blockIdx.y;
    const int cbase = xh * HALFW_;

    uint4 w[9];
    #pragma unroll
    for (int tp = 0; tp < 9; ++tp)
        w[tp] = *(const uint4*)&Wp[((size_t)tp * C_ + c) * NW_ + half2];

    const int rt = (oy == 0) ? 0 : ((oy == H_ - 1) ? 2 : 1);
    const int cL = corr[(rt * 3 + 0) * C_ + c];
    const int cM = corr[(rt * 3 + 1) * C_ + c];
    const int cR = corr[(rt * 3 + 2) * C_ + c];

    {
        ulonglong2* dst = (ulonglong2*)sx;
        for (int i = t; i < 3 * SLAB_ * 2; i += 256) {
            int r = i / (SLAB_ * 2), rem = i - r * (SLAB_ * 2);
            const ulonglong2* src = (const ulonglong2*)
                (Xp + (((size_t)n * PH_ + oy + r) * PW_ + cbase) * NW_);
            dst[r * SLAB_ * 2 + rem] = src[rem];
        }
    }
    __syncthreads();

    int ss = 0, qq = 0;
    const size_t rowbase = (((size_t)n * H_ + oy) * W_) * C_ + c;

    #pragma unroll 1
    for (int ox = 0; ox < HALFW_; ox += 4) {
        u32 on0 = 0, on1 = 0, on2 = 0, on3 = 0;
        int acc0 = 0, acc1 = 0, acc2 = 0, acc3 = 0;
        #pragma unroll
        for (int ky = 0; ky < 3; ++ky) {
            const u64* rp = &sx[(ky * SLAB_ + ox) * NW_ + half2];
            const uint4 c0 = *(const uint4*)(rp);
            const uint4 c1 = *(const uint4*)(rp + NW_);
            const uint4 c2 = *(const uint4*)(rp + 2 * NW_);
            const uint4 c3 = *(const uint4*)(rp + 3 * NW_);
            const uint4 c4 = *(const uint4*)(rp + 4 * NW_);
            const uint4 c5 = *(const uint4*)(rp + 5 * NW_);
            const int k3 = ky * 3;
            TAP(acc0, on0, c0, w[k3 + 0])
            TAP(acc0, on0, c1, w[k3 + 1])
            TAP(acc0, on0, c2, w[k3 + 2])
            TAP(acc1, on1, c1, w[k3 + 0])
            TAP(acc1, on1, c2, w[k3 + 1])
            TAP(acc1, on1, c3, w[k3 + 2])
            TAP(acc2, on2, c2, w[k3 + 0])
            TAP(acc2, on2, c3, w[k3 + 1])
            TAP(acc2, on2, c4, w[k3 + 2])
            TAP(acc3, on3, c3, w[k3 + 0])
            TAP(acc3, on3, c4, w[k3 + 1])
            TAP(acc3, on3, c5, w[k3 + 2])
        }
        const int f0 = 2 * acc0 + __popc(on0);   // <=1152 each
        const int f1 = 2 * acc1 + __popc(on1);
        const int f2 = 2 * acc2 + __popc(on2);
        const int f3 = 2 * acc3 + __popc(on3);
        unsigned p01 = (unsigned)f0 | ((unsigned)f1 << 16);
        unsigned p23 = (unsigned)f2 | ((unsigned)f3 << 16);
        p01 += __shfl_xor_sync(0xffffffffu, p01, 1);   // merge halves
        p23 += __shfl_xor_sync(0xffffffffu, p23, 1);
        // even thread finalizes pixels ox,ox+1; odd finalizes ox+2,ox+3
        const unsigned fsel = half ? p23 : p01;
        const int gx = cbase + ox + half * 2;
        const int fa = (int)(fsel & 0xffffu);
        const int fb = (int)(fsel >> 16);
        const int ca = (gx == 0) ? cL : ((gx == W_ - 1) ? cR : cM);
        const int cb = (gx + 1 == W_ - 1) ? cR : cM;
        const int sa = 2304 - 2 * fa - ca;
        const int sb = 2304 - 2 * fb - cb;
        const size_t pb = rowbase + (size_t)gx * C_;
        S[pb]      = (short)sa;
        S[pb + C_] = (short)sb;
        ss += sa + sb;
        qq += sa * sa + sb * sb;
    }
    atomicAdd(&sum[c], (ull)(long long)ss);
    atomicAdd(&sq[c],  (ull)(long long)qq);
}

// ============================ thresh (fp32 params) ============================
__global__ void thresh_ballot_k(const short* __restrict__ S,
                                const float* __restrict__ a, const float* __restrict__ b,
                                u64* __restrict__ Xp2) {
    int c = threadIdx.x;
    int py = blockIdx.x, n = blockIdx.y;
    int warp = c >> 5, lane = c & 31;
    float av = a[c], bv = b[c];
    bool rowv = (py >= 1 && py <= H_);
    #pragma unroll 4
    for (int px = 0; px < PW_; ++px) {
        unsigned bit = 0u;
        if (rowv && px >= 1 && px <= W_) {
            int v = S[(((size_t)n * H_ + (py - 1)) * W_ + (px - 1)) * C_ + c];
            bit = (av * (float)v + bv > 0.0f) ? 1u : 0u;
        }
        unsigned m = __ballot_sync(0xffffffffu, bit);
        if (lane == 0)
            ((unsigned*)(Xp2 + (((size_t)n * PH_ + py) * PW_ + px) * NW_))[warp] = m;
    }
}

// ============================ final (fp32 params, float4 I/O) ============================
__global__ __launch_bounds__(256)
void final_k(const short* __restrict__ S2,
             const float* __restrict__ a, const float* __restrict__ b,
             const float* __restrict__ x, float* __restrict__ out) {
    __shared__ short s[32][258];
    __shared__ float sa[C_], sb[C_];
    const int n = blockIdx.y, pt = blockIdx.x;
    const int tid = threadIdx.x;

    sa[tid] = a[tid];
    sb[tid] = b[tid];
    const short2* src = (const short2*)(S2 + ((size_t)n * PIX_ + pt * 32) * C_);
    #pragma unroll
    for (int i = tid; i < 32 * 128; i += 256) {
        int r = i >> 7, c2 = i & 127;
        short2 v = src[(size_t)r * 128 + c2];
        s[r][c2 * 2]     = v.x;
        s[r][c2 * 2 + 1] = v.y;
    }
    __syncthreads();

    const int pg = tid & 7;
    const int c0 = tid >> 3;
    const int p0 = pt * 32 + pg * 4;
    #pragma unroll
    for (int cc = c0; cc < C_; cc += 32) {
        const float av = sa[cc], bv = sb[cc];
        const size_t oi = ((size_t)n * C_ + cc) * PIX_ + p0;
        const float4 xv = *(const float4*)(x + oi);
        float4 o;
        o.x = fminf(1.f, fmaxf(-1.f, av * (float)s[pg * 4 + 0][cc] + bv + xv.x));
        o.y = fminf(1.f, fmaxf(-1.f, av * (float)s[pg * 4 + 1][cc] + bv + xv.y));
        o.z = fminf(1.f, fmaxf(-1.f, av * (float)s[pg * 4 + 2][cc] + bv + xv.z));
        o.w = fminf(1.f, fmaxf(-1.f, av * (float)s[pg * 4 + 3][cc] + bv + xv.w));
        *(float4*)(out + oi) = o;
    }
}

// ============================ launch ============================
extern "C" void kernel_launch(void* const* d_in, const int* in_sizes, int n_in,
                              void* d_out, int out_size) {
    const float* x  = (const float*)d_in[0];
    const float* w1 = (const float*)d_in[1];
    const float* g1 = (const float*)d_in[2];
    const float* b1 = (const float*)d_in[3];
    const float* w2 = (const float*)d_in[4];
    const float* g2 = (const float*)d_in[5];
    const float* b2 = (const float*)d_in[6];
    float* out = (float*)d_out;

    void *pX1, *pX2, *pW1, *pW2, *pc1, *pc2, *pS1, *pS2;
    void *psum1, *psq1, *psum2, *psq2, *pa1, *pb1, *pa2, *pb2;
    cudaGetSymbolAddress(&pX1, g_Xp1);  cudaGetSymbolAddress(&pX2, g_Xp2);
    cudaGetSymbolAddress(&pW1, g_Wp1);  cudaGetSymbolAddress(&pW2, g_Wp2);
    cudaGetSymbolAddress(&pc1, g_c1);   cudaGetSymbolAddress(&pc2, g_c2);
    cudaGetSymbolAddress(&pS1, g_S1);   cudaGetSymbolAddress(&pS2, g_S2);
    cudaGetSymbolAddress(&psum1, g_sum1); cudaGetSymbolAddress(&psq1, g_sq1);
    cudaGetSymbolAddress(&psum2, g_sum2); cudaGetSymbolAddress(&psq2, g_sq2);
    cudaGetSymbolAddress(&pa1, g_a1);   cudaGetSymbolAddress(&pb1, g_b1);
    cudaGetSymbolAddress(&pa2, g_a2);   cudaGetSymbolAddress(&pb2, g_b2);

    // conv1 stays launch #3 (the one ncu profiles)
    pack_w_k<<<18, 256>>>(w1, w2, (u64*)pW1, (u64*)pW2);             // #0 (zeros stats)
    corr_w_k<<<2, 256>>>();                                          // #1
    pack_x_k<<<dim3(PH_, N_), dim3(PW_, NW_)>>>(x, (u64*)pX1);       // #2
    conv_pop_k<<<dim3(H_ * 2, N_, 2), 256>>>((const u64*)pX1, (const u64*)pW1,   // #3
                                             (const int*)pc1, (short*)pS1,
                                             (ull*)psum1, (ull*)psq1);
    bnparams_k<<<1, 256>>>((const ull*)psum1, (const ull*)psq1, g1, b1,
                           (float*)pa1, (float*)pb1);                // #4
    thresh_ballot_k<<<dim3(PH_, N_), 256>>>((const short*)pS1,
        (const float*)pa1, (const float*)pb1, (u64*)pX2);            // #5
    conv_pop_k<<<dim3(H_ * 2, N_, 2), 256>>>((const u64*)pX2, (const u64*)pW2,   // #6
                                             (const int*)pc2, (short*)pS2,
                                             (ull*)psum2, (ull*)psq2);
    bnparams_k<<<1, 256>>>((const ull*)psum2, (const ull*)psq2, g2, b2,
                           (float*)pa2, (float*)pb2);                // #7
    final_k<<<dim3(PIX_ / 32, N_), 256>>>((const short*)pS2,
        (const float*)pa2, (const float*)pb2, x, out);               // #8
}